// round 4
// baseline (speedup 1.0000x reference)
#include <cuda_runtime.h>
#include <math.h>

// Problem constants
#define BB 2
#define NN 2048
#define DD 512
#define HH 8
#define DHH 64
#define PP 64

// Scratch: q,k,v in [B,H,N,DH], att in [B,N,H*DH]
__device__ float g_q[BB * HH * NN * DHH];
__device__ float g_k[BB * HH * NN * DHH];
__device__ float g_v[BB * HH * NN * DHH];
__device__ float g_att[BB * NN * HH * DHH];

// ---------------------------------------------------------------------------
// helpers
// ---------------------------------------------------------------------------
__device__ __forceinline__ unsigned f2tf(float x) {
    unsigned r;
    asm("cvt.rna.tf32.f32 %0, %1;" : "=r"(r) : "f"(x));
    return r;
}
__device__ __forceinline__ float f2tff(float x) {
    unsigned r;
    asm("cvt.rna.tf32.f32 %0, %1;" : "=r"(r) : "f"(x));
    return __uint_as_float(r);
}
__device__ __forceinline__ float ex2f(float x) {
    float r;
    asm("ex2.approx.f32 %0, %1;" : "=f"(r) : "f"(x));
    return r;
}
__device__ __forceinline__ void mma8(float c[4], const unsigned a[4], const unsigned b[2]) {
    asm volatile(
        "mma.sync.aligned.m16n8k8.row.col.f32.tf32.tf32.f32 "
        "{%0,%1,%2,%3}, {%4,%5,%6,%7}, {%8,%9}, {%0,%1,%2,%3};\n"
        : "+f"(c[0]), "+f"(c[1]), "+f"(c[2]), "+f"(c[3])
        : "r"(a[0]), "r"(a[1]), "r"(a[2]), "r"(a[3]), "r"(b[0]), "r"(b[1]));
}
__device__ __forceinline__ void cp16(unsigned s, const void* g) {
    asm volatile("cp.async.ca.shared.global [%0], [%1], 16;" :: "r"(s), "l"(g));
}
#define CP_COMMIT() asm volatile("cp.async.commit_group;")
#define CP_WAIT1()  asm volatile("cp.async.wait_group 1;")

// ---------------------------------------------------------------------------
// GEMM kernels: tf32 mma, CTA 128(m) x 64(n), 8 warps, register-staged
// double buffering of gmem loads.
// ---------------------------------------------------------------------------
#define AS_STRIDE 36
#define BS_STRIDE 36

#define GEMM_LOAD_TILE(Aglob, W, KT)                                            \
    do {                                                                        \
        _Pragma("unroll")                                                       \
        for (int i = 0; i < 4; i++) {                                           \
            int f = tid + i * 256;                                              \
            int row = f >> 3, c4 = (f & 7) << 2;                                \
            aReg[i] = *(const float4*)&Aglob[(size_t)(rowBase + row) * DD + (KT) + c4]; \
        }                                                                       \
        _Pragma("unroll")                                                       \
        for (int i = 0; i < 8; i++) {                                           \
            int f = tid + i * 256;                                              \
            int k = f >> 6, n = f & 63;                                         \
            bReg[i] = W[(size_t)((KT) + k) * DD + colBase + n];                 \
        }                                                                       \
    } while (0)

#define GEMM_STS_TILE()                                                         \
    do {                                                                        \
        _Pragma("unroll")                                                       \
        for (int i = 0; i < 4; i++) {                                           \
            int f = tid + i * 256;                                              \
            int row = f >> 3, c4 = (f & 7) << 2;                                \
            As[row * AS_STRIDE + c4 + 0] = f2tff(aReg[i].x);                    \
            As[row * AS_STRIDE + c4 + 1] = f2tff(aReg[i].y);                    \
            As[row * AS_STRIDE + c4 + 2] = f2tff(aReg[i].z);                    \
            As[row * AS_STRIDE + c4 + 3] = f2tff(aReg[i].w);                    \
        }                                                                       \
        _Pragma("unroll")                                                       \
        for (int i = 0; i < 8; i++) {                                           \
            int f = tid + i * 256;                                              \
            int k = f >> 6, n = f & 63;                                         \
            Bs[n * BS_STRIDE + k] = f2tff(bReg[i]);                             \
        }                                                                       \
    } while (0)

#define GEMM_MMA_PHASE()                                                        \
    do {                                                                        \
        _Pragma("unroll")                                                       \
        for (int ks = 0; ks < 4; ks++) {                                        \
            unsigned a[2][4];                                                   \
            _Pragma("unroll")                                                   \
            for (int mi = 0; mi < 2; mi++) {                                    \
                int mb = wm * 32 + mi * 16;                                     \
                a[mi][0] = __float_as_uint(As[(mb + g)     * AS_STRIDE + ks * 8 + t]);     \
                a[mi][1] = __float_as_uint(As[(mb + g + 8) * AS_STRIDE + ks * 8 + t]);     \
                a[mi][2] = __float_as_uint(As[(mb + g)     * AS_STRIDE + ks * 8 + t + 4]); \
                a[mi][3] = __float_as_uint(As[(mb + g + 8) * AS_STRIDE + ks * 8 + t + 4]); \
            }                                                                   \
            _Pragma("unroll")                                                   \
            for (int ni = 0; ni < 4; ni++) {                                    \
                int n = wn * 32 + ni * 8 + g;                                   \
                unsigned bb[2];                                                 \
                bb[0] = __float_as_uint(Bs[n * BS_STRIDE + ks * 8 + t]);        \
                bb[1] = __float_as_uint(Bs[n * BS_STRIDE + ks * 8 + t + 4]);    \
                mma8(acc[0][ni], a[0], bb);                                     \
                mma8(acc[1][ni], a[1], bb);                                     \
            }                                                                   \
        }                                                                       \
    } while (0)

__global__ __launch_bounds__(256) void qkv_mma(
    const float* __restrict__ x,
    const float* __restrict__ Wq,
    const float* __restrict__ Wk,
    const float* __restrict__ Wv)
{
    const float* W = (blockIdx.z == 0) ? Wq : ((blockIdx.z == 1) ? Wk : Wv);
    float* out = (blockIdx.z == 0) ? g_q : ((blockIdx.z == 1) ? g_k : g_v);

    __shared__ float As[128 * AS_STRIDE];
    __shared__ float Bs[64 * BS_STRIDE];

    const int tid = threadIdx.x;
    const int w = tid >> 5, lane = tid & 31;
    const int g = lane >> 2, t = lane & 3;
    const int wm = w >> 1, wn = w & 1;

    const int rowBase = blockIdx.y * 128;
    const int colBase = blockIdx.x * 64;

    float4 aReg[4];
    float  bReg[8];
    float acc[2][4][4] = {};

    GEMM_LOAD_TILE(x, W, 0);

    for (int kt = 0; kt < DD; kt += 32) {
        GEMM_STS_TILE();
        __syncthreads();
        if (kt + 32 < DD) GEMM_LOAD_TILE(x, W, kt + 32);
        GEMM_MMA_PHASE();
        __syncthreads();
    }

    // Epilogue: scatter to [b][h][n][dh]
    #pragma unroll
    for (int mi = 0; mi < 2; mi++) {
        #pragma unroll
        for (int ni = 0; ni < 4; ni++) {
            int gm0 = rowBase + wm * 32 + mi * 16 + g;
            int gn  = colBase + wn * 32 + ni * 8 + 2 * t;
            int h = gn >> 6, dh = gn & 63;
            {
                int b = gm0 >> 11, n = gm0 & (NN - 1);
                float2 v; v.x = acc[mi][ni][0]; v.y = acc[mi][ni][1];
                *(float2*)&out[(size_t)(((b * HH + h) * NN) + n) * DHH + dh] = v;
            }
            {
                int gm1 = gm0 + 8;
                int b = gm1 >> 11, n = gm1 & (NN - 1);
                float2 v; v.x = acc[mi][ni][2]; v.y = acc[mi][ni][3];
                *(float2*)&out[(size_t)(((b * HH + h) * NN) + n) * DHH + dh] = v;
            }
        }
    }
}

__global__ __launch_bounds__(256) void out_mma(
    const float* __restrict__ Wo,
    const float* __restrict__ bo,
    float* __restrict__ y)
{
    __shared__ float As[128 * AS_STRIDE];
    __shared__ float Bs[64 * BS_STRIDE];

    const int tid = threadIdx.x;
    const int w = tid >> 5, lane = tid & 31;
    const int g = lane >> 2, t = lane & 3;
    const int wm = w >> 1, wn = w & 1;

    const int rowBase = blockIdx.y * 128;
    const int colBase = blockIdx.x * 64;

    float4 aReg[4];
    float  bReg[8];
    float acc[2][4][4] = {};

    GEMM_LOAD_TILE(g_att, Wo, 0);

    for (int kt = 0; kt < DD; kt += 32) {
        GEMM_STS_TILE();
        __syncthreads();
        if (kt + 32 < DD) GEMM_LOAD_TILE(g_att, Wo, kt + 32);
        GEMM_MMA_PHASE();
        __syncthreads();
    }

    #pragma unroll
    for (int mi = 0; mi < 2; mi++) {
        #pragma unroll
        for (int ni = 0; ni < 4; ni++) {
            int gm0 = rowBase + wm * 32 + mi * 16 + g;
            int gn  = colBase + wn * 32 + ni * 8 + 2 * t;
            float2 bov = *(const float2*)&bo[gn];
            float2 v0; v0.x = acc[mi][ni][0] + bov.x; v0.y = acc[mi][ni][1] + bov.y;
            float2 v1; v1.x = acc[mi][ni][2] + bov.x; v1.y = acc[mi][ni][3] + bov.y;
            *(float2*)&y[(size_t)gm0 * DD + gn] = v0;
            *(float2*)&y[(size_t)(gm0 + 8) * DD + gn] = v1;
        }
    }
}

// ---------------------------------------------------------------------------
// Flash attention: tf32 mma, CTA = (b, h, 128 queries), 8 warps.
// K/V tiles double-buffered in smem via cp.async (K/V are raw fp32 operands).
// ---------------------------------------------------------------------------
#define KS_STRIDE 68
#define VS_STRIDE 72
#define PS_STRIDE 68

#define ATT_SMEM_FLOATS (2*64*KS_STRIDE + 2*64*VS_STRIDE + 128*PS_STRIDE + 132 + 132)

__global__ __launch_bounds__(256) void attention_mma(
    const float* __restrict__ rel_pos,
    const float* __restrict__ c_emb)
{
    extern __shared__ float sm[];
    float* Ks    = sm;                          // [2][64][68]
    float* Vs    = Ks + 2 * 64 * KS_STRIDE;     // [2][64][72]
    float* Ps    = Vs + 2 * 64 * VS_STRIDE;     // [128][68]
    float* relS  = Ps + 128 * PS_STRIDE;        // [129] pre-scaled
    float* gateS = relS + 132;                  // [129]

    const int qb  = blockIdx.x;
    const int h   = blockIdx.y;
    const int b   = blockIdx.z;
    const int tid = threadIdx.x;
    const int w    = tid >> 5;
    const int lane = tid & 31;
    const int g    = lane >> 2;
    const int t    = lane & 3;

    const float* qptr = g_q + (size_t)((b * HH + h) * NN) * DHH;
    const float* kptr = g_k + (size_t)((b * HH + h) * NN) * DHH;
    const float* vptr = g_v + (size_t)((b * HH + h) * NN) * DHH;

    const int i0 = qb * 128 + w * 16;
    const float sc = 0.125f * 1.4426950408889634f;  // log2(e)/8

    const unsigned ksBase = (unsigned)__cvta_generic_to_shared(Ks);
    const unsigned vsBase = (unsigned)__cvta_generic_to_shared(Vs);

    // cp.async coords: 4 rows per thread, one float4 each, per tile
    const int ldRow = tid >> 4;          // 0..15 (+16*r)
    const int ldC4  = (tid & 15) << 2;   // 0..60

    #define LOAD_KV(KB, BUF)                                                     \
        do {                                                                     \
            _Pragma("unroll")                                                    \
            for (int r = 0; r < 4; r++) {                                        \
                int row = r * 16 + ldRow;                                        \
                cp16(ksBase + (unsigned)(((BUF) * 64 * KS_STRIDE + row * KS_STRIDE + ldC4) * 4), \
                     &kptr[(size_t)((KB) + row) * DHH + ldC4]);                  \
                cp16(vsBase + (unsigned)(((BUF) * 64 * VS_STRIDE + row * VS_STRIDE + ldC4) * 4), \
                     &vptr[(size_t)((KB) + row) * DHH + ldC4]);                  \
            }                                                                    \
        } while (0)

    for (int u = tid; u < 129; u += 256) {
        relS[u]  = rel_pos[u * HH + h] * sc;
        gateS[u] = c_emb[u * HH + h];
    }

    LOAD_KV(0, 0);
    CP_COMMIT();

    // Q fragments in registers, pre-scaled + tf32-rounded
    unsigned qa[8][4];
    #pragma unroll
    for (int kc = 0; kc < 8; kc++) {
        qa[kc][0] = f2tf(qptr[(i0 + g)     * DHH + kc * 8 + t]     * sc);
        qa[kc][1] = f2tf(qptr[(i0 + g + 8) * DHH + kc * 8 + t]     * sc);
        qa[kc][2] = f2tf(qptr[(i0 + g)     * DHH + kc * 8 + t + 4] * sc);
        qa[kc][3] = f2tf(qptr[(i0 + g + 8) * DHH + kc * 8 + t + 4] * sc);
    }

    float m0 = -1e30f, m1 = -1e30f, l0 = 0.f, l1 = 0.f;
    float o[8][4];
    #pragma unroll
    for (int nt = 0; nt < 8; nt++)
        #pragma unroll
        for (int j = 0; j < 4; j++) o[nt][j] = 0.f;

    for (int it = 0; it < NN / 64; it++) {
        const int kb = it * 64;
        const int buf = it & 1;
        const float* Ksb = Ks + buf * 64 * KS_STRIDE;
        const float* Vsb = Vs + buf * 64 * VS_STRIDE;

        if (it + 1 < NN / 64) LOAD_KV(kb + 64, buf ^ 1);
        CP_COMMIT();
        CP_WAIT1();
        __syncthreads();   // tile it visible to all warps

        // S = Q K^T
        float s[8][4];
        #pragma unroll
        for (int nt = 0; nt < 8; nt++) {
            float c[4] = {0.f, 0.f, 0.f, 0.f};
            #pragma unroll
            for (int kc = 0; kc < 8; kc++) {
                unsigned bb[2];
                bb[0] = __float_as_uint(Ksb[(nt * 8 + g) * KS_STRIDE + kc * 8 + t]);
                bb[1] = __float_as_uint(Ksb[(nt * 8 + g) * KS_STRIDE + kc * 8 + t + 4]);
                mma8(c, qa[kc], bb);
            }
            s[nt][0] = c[0]; s[nt][1] = c[1]; s[nt][2] = c[2]; s[nt][3] = c[3];
        }

        // Bias + online softmax (exp2 domain)
        const bool farhi = (kb >= i0 + 79);
        const bool farlo = (kb + 127 <= i0);
        const bool far = farhi || farlo;
        const float cb = farhi ? relS[128]  : relS[0];
        const float cg = farhi ? gateS[128] : gateS[0];

        float mx0 = -1e30f, mx1 = -1e30f;
        #pragma unroll
        for (int nt = 0; nt < 8; nt++) {
            if (far) {
                s[nt][0] += cb; s[nt][1] += cb; s[nt][2] += cb; s[nt][3] += cb;
            } else {
                int j0 = kb + nt * 8 + 2 * t;
                int d0 = j0 - (i0 + g);
                int d1 = d0 - 8;
                s[nt][0] += relS[min(max(d0,     -PP), PP) + PP];
                s[nt][1] += relS[min(max(d0 + 1, -PP), PP) + PP];
                s[nt][2] += relS[min(max(d1,     -PP), PP) + PP];
                s[nt][3] += relS[min(max(d1 + 1, -PP), PP) + PP];
            }
            mx0 = fmaxf(mx0, fmaxf(s[nt][0], s[nt][1]));
            mx1 = fmaxf(mx1, fmaxf(s[nt][2], s[nt][3]));
        }
        mx0 = fmaxf(mx0, __shfl_xor_sync(0xffffffffu, mx0, 1));
        mx0 = fmaxf(mx0, __shfl_xor_sync(0xffffffffu, mx0, 2));
        mx1 = fmaxf(mx1, __shfl_xor_sync(0xffffffffu, mx1, 1));
        mx1 = fmaxf(mx1, __shfl_xor_sync(0xffffffffu, mx1, 2));

        float mn0 = fmaxf(m0, mx0), mn1 = fmaxf(m1, mx1);
        float corr0 = ex2f(m0 - mn0), corr1 = ex2f(m1 - mn1);

        float rs0 = 0.f, rs1 = 0.f;
        const int prow0 = (w * 16 + g) * PS_STRIDE;
        const int prow1 = (w * 16 + g + 8) * PS_STRIDE;
        #pragma unroll
        for (int nt = 0; nt < 8; nt++) {
            float p00 = ex2f(s[nt][0] - mn0);
            float p01 = ex2f(s[nt][1] - mn0);
            float p10 = ex2f(s[nt][2] - mn1);
            float p11 = ex2f(s[nt][3] - mn1);
            rs0 += p00 + p01;
            rs1 += p10 + p11;
            float g00, g01, g10, g11;
            if (far) {
                g00 = g01 = g10 = g11 = cg;
            } else {
                int j0 = kb + nt * 8 + 2 * t;
                int d0 = j0 - (i0 + g);
                int d1 = d0 - 8;
                g00 = gateS[min(max(d0,     -PP), PP) + PP];
                g01 = gateS[min(max(d0 + 1, -PP), PP) + PP];
                g10 = gateS[min(max(d1,     -PP), PP) + PP];
                g11 = gateS[min(max(d1 + 1, -PP), PP) + PP];
            }
            float2 w0, w1;
            w0.x = __uint_as_float(f2tf(p00 * g00));
            w0.y = __uint_as_float(f2tf(p01 * g01));
            w1.x = __uint_as_float(f2tf(p10 * g10));
            w1.y = __uint_as_float(f2tf(p11 * g11));
            *(float2*)&Ps[prow0 + nt * 8 + 2 * t] = w0;
            *(float2*)&Ps[prow1 + nt * 8 + 2 * t] = w1;
        }
        rs0 += __shfl_xor_sync(0xffffffffu, rs0, 1);
        rs0 += __shfl_xor_sync(0xffffffffu, rs0, 2);
        rs1 += __shfl_xor_sync(0xffffffffu, rs1, 1);
        rs1 += __shfl_xor_sync(0xffffffffu, rs1, 2);

        l0 = l0 * corr0 + rs0; m0 = mn0;
        l1 = l1 * corr1 + rs1; m1 = mn1;

        #pragma unroll
        for (int nt = 0; nt < 8; nt++) {
            o[nt][0] *= corr0; o[nt][1] *= corr0;
            o[nt][2] *= corr1; o[nt][3] *= corr1;
        }

        __syncwarp();  // Ps rows are per-warp private

        // O += P V
        #pragma unroll
        for (int kc = 0; kc < 8; kc++) {
            unsigned a[4];
            a[0] = __float_as_uint(Ps[prow0 + kc * 8 + t]);
            a[1] = __float_as_uint(Ps[prow1 + kc * 8 + t]);
            a[2] = __float_as_uint(Ps[prow0 + kc * 8 + t + 4]);
            a[3] = __float_as_uint(Ps[prow1 + kc * 8 + t + 4]);
            #pragma unroll
            for (int nt = 0; nt < 8; nt++) {
                unsigned bb[2];
                bb[0] = __float_as_uint(Vsb[(kc * 8 + t)     * VS_STRIDE + nt * 8 + g]);
                bb[1] = __float_as_uint(Vsb[(kc * 8 + t + 4) * VS_STRIDE + nt * 8 + g]);
                mma8(o[nt], a, bb);
            }
        }
        __syncthreads();  // everyone done reading buf before it is refilled
    }

    // Finalize
    float inv0 = 1.f / l0, inv1 = 1.f / l1;
    const size_t base = ((size_t)b * NN) * (HH * DHH) + h * DHH;
    const int r0 = i0 + g, r1 = i0 + g + 8;
    #pragma unroll
    for (int nt = 0; nt < 8; nt++) {
        float2 v0, v1;
        v0.x = o[nt][0] * inv0; v0.y = o[nt][1] * inv0;
        v1.x = o[nt][2] * inv1; v1.y = o[nt][3] * inv1;
        *(float2*)&g_att[base + (size_t)r0 * (HH * DHH) + nt * 8 + 2 * t] = v0;
        *(float2*)&g_att[base + (size_t)r1 * (HH * DHH) + nt * 8 + 2 * t] = v1;
    }
}

// ---------------------------------------------------------------------------
extern "C" void kernel_launch(void* const* d_in, const int* in_sizes, int n_in,
                              void* d_out, int out_size)
{
    const float* x       = (const float*)d_in[0];
    const float* Wq      = (const float*)d_in[1];
    const float* Wk      = (const float*)d_in[2];
    const float* Wv      = (const float*)d_in[3];
    const float* rel_pos = (const float*)d_in[4];
    const float* c_emb   = (const float*)d_in[5];
    const float* Wo      = (const float*)d_in[6];
    const float* bo      = (const float*)d_in[7];
    float* y             = (float*)d_out;

    dim3 gQKV(DD / 64, (BB * NN) / 128, 3);
    qkv_mma<<<gQKV, 256>>>(x, Wq, Wk, Wv);

    size_t attSmem = (size_t)ATT_SMEM_FLOATS * sizeof(float);
    cudaFuncSetAttribute(attention_mma,
                         cudaFuncAttributeMaxDynamicSharedMemorySize,
                         (int)attSmem);
    dim3 gAtt(NN / 128, HH, BB);
    attention_mma<<<gAtt, 256, attSmem>>>(rel_pos, c_emb);

    dim3 gOut(DD / 64, (BB * NN) / 128);
    out_mma<<<gOut, 256>>>(Wo, bo, y);
}

// round 5
// speedup vs baseline: 1.4790x; 1.4790x over previous
#include <cuda_runtime.h>
#include <math.h>

// Problem constants
#define BB 2
#define NN 2048
#define DD 512
#define HH 8
#define DHH 64
#define PP 64

// Scratch: q,k,v in [B,H,N,DH], att in [B,N,H*DH], rounded operands
__device__ float g_q[BB * HH * NN * DHH];
__device__ float g_k[BB * HH * NN * DHH];
__device__ float g_v[BB * HH * NN * DHH];
__device__ float g_att[BB * NN * HH * DHH];
__device__ float g_xr[BB * NN * DD];
__device__ float g_wqr[DD * DD];
__device__ float g_wkr[DD * DD];
__device__ float g_wvr[DD * DD];
__device__ float g_wor[DD * DD];

// ---------------------------------------------------------------------------
// helpers
// ---------------------------------------------------------------------------
__device__ __forceinline__ unsigned f2tf(float x) {
    unsigned r;
    asm("cvt.rna.tf32.f32 %0, %1;" : "=r"(r) : "f"(x));
    return r;
}
__device__ __forceinline__ float f2tff(float x) {
    unsigned r;
    asm("cvt.rna.tf32.f32 %0, %1;" : "=r"(r) : "f"(x));
    return __uint_as_float(r);
}
__device__ __forceinline__ float ex2f(float x) {
    float r;
    asm("ex2.approx.f32 %0, %1;" : "=f"(r) : "f"(x));
    return r;
}
__device__ __forceinline__ void mma8(float c[4], const unsigned a[4], const unsigned b[2]) {
    asm volatile(
        "mma.sync.aligned.m16n8k8.row.col.f32.tf32.tf32.f32 "
        "{%0,%1,%2,%3}, {%4,%5,%6,%7}, {%8,%9}, {%0,%1,%2,%3};\n"
        : "+f"(c[0]), "+f"(c[1]), "+f"(c[2]), "+f"(c[3])
        : "r"(a[0]), "r"(a[1]), "r"(a[2]), "r"(a[3]), "r"(b[0]), "r"(b[1]));
}
__device__ __forceinline__ void cp16(unsigned s, const void* g) {
    asm volatile("cp.async.ca.shared.global [%0], [%1], 16;" :: "r"(s), "l"(g));
}
#define CP_COMMIT() asm volatile("cp.async.commit_group;")
#define CP_WAIT1()  asm volatile("cp.async.wait_group 1;")

// ---------------------------------------------------------------------------
// Prep: tf32-round x and weights (elementwise, float4).
// blocks 0..2047: x (524288 float4); then 256 blocks per weight matrix.
// ---------------------------------------------------------------------------
__global__ __launch_bounds__(256) void round_prep(
    const float* __restrict__ x,
    const float* __restrict__ wq,
    const float* __restrict__ wk,
    const float* __restrict__ wv,
    const float* __restrict__ wo)
{
    int b = blockIdx.x;
    const float4* src;
    float4* dst;
    int idx;
    if (b < 2048) {
        src = (const float4*)x; dst = (float4*)g_xr;
        idx = b * 256 + threadIdx.x;
    } else {
        int s = (b - 2048) >> 8;
        idx = ((b - 2048) & 255) * 256 + threadIdx.x;
        src = (const float4*)(s == 0 ? wq : (s == 1 ? wk : (s == 2 ? wv : wo)));
        dst = (float4*)(s == 0 ? g_wqr : (s == 1 ? g_wkr : (s == 2 ? g_wvr : g_wor)));
    }
    float4 v = src[idx];
    v.x = f2tff(v.x); v.y = f2tff(v.y); v.z = f2tff(v.z); v.w = f2tff(v.w);
    dst[idx] = v;
}

// ---------------------------------------------------------------------------
// GEMM: tf32 mma, CTA 128(m) x 64(n), 8 warps, 3-stage cp.async pipeline.
// A stage [128][36] ([m][k]), B stage [32][72] ([k][n]) — no transpose.
// ---------------------------------------------------------------------------
#define GA_STRIDE 36
#define GB_STRIDE 72
#define STAGE_A (128 * GA_STRIDE)
#define STAGE_B (32 * GB_STRIDE)
#define STAGE_FLOATS (STAGE_A + STAGE_B)
#define GEMM_SMEM_BYTES (3 * STAGE_FLOATS * 4)

#define G_LOAD(Asrc, Bsrc, KT, STG)                                              \
    do {                                                                         \
        unsigned sa = smemBase + (unsigned)((STG) * STAGE_FLOATS * 4);           \
        _Pragma("unroll")                                                        \
        for (int i = 0; i < 4; i++) {                                            \
            int f = tid + i * 256;                                               \
            int row = f >> 3, c4 = (f & 7) << 2;                                 \
            cp16(sa + (unsigned)((row * GA_STRIDE + c4) * 4),                    \
                 &Asrc[(size_t)(rowBase + row) * DD + (KT) + c4]);               \
        }                                                                        \
        unsigned sb = sa + STAGE_A * 4;                                          \
        _Pragma("unroll")                                                        \
        for (int i = 0; i < 2; i++) {                                            \
            int f = tid + i * 256;                                               \
            int row = f >> 4, c4 = (f & 15) << 2;                                \
            cp16(sb + (unsigned)((row * GB_STRIDE + c4) * 4),                    \
                 &Bsrc[(size_t)((KT) + row) * DD + colBase + c4]);               \
        }                                                                        \
    } while (0)

#define G_MMA(STG)                                                               \
    do {                                                                         \
        const float* As = smem + (STG) * STAGE_FLOATS;                           \
        const float* Bs = As + STAGE_A;                                          \
        _Pragma("unroll")                                                        \
        for (int ks = 0; ks < 4; ks++) {                                         \
            unsigned a[2][4];                                                    \
            _Pragma("unroll")                                                    \
            for (int mi = 0; mi < 2; mi++) {                                     \
                int mb = wm * 32 + mi * 16;                                      \
                a[mi][0] = __float_as_uint(As[(mb + g)     * GA_STRIDE + ks * 8 + t]);     \
                a[mi][1] = __float_as_uint(As[(mb + g + 8) * GA_STRIDE + ks * 8 + t]);     \
                a[mi][2] = __float_as_uint(As[(mb + g)     * GA_STRIDE + ks * 8 + t + 4]); \
                a[mi][3] = __float_as_uint(As[(mb + g + 8) * GA_STRIDE + ks * 8 + t + 4]); \
            }                                                                    \
            _Pragma("unroll")                                                    \
            for (int ni = 0; ni < 4; ni++) {                                     \
                int n = wn * 32 + ni * 8 + g;                                    \
                unsigned bb[2];                                                  \
                bb[0] = __float_as_uint(Bs[(ks * 8 + t)     * GB_STRIDE + n]);   \
                bb[1] = __float_as_uint(Bs[(ks * 8 + t + 4) * GB_STRIDE + n]);   \
                mma8(acc[0][ni], a[0], bb);                                      \
                mma8(acc[1][ni], a[1], bb);                                      \
            }                                                                    \
        }                                                                        \
    } while (0)

#define G_MAINLOOP(Asrc, Bsrc)                                                   \
    do {                                                                         \
        G_LOAD(Asrc, Bsrc, 0, 0);  CP_COMMIT();                                  \
        G_LOAD(Asrc, Bsrc, 32, 1); CP_COMMIT();                                  \
        _Pragma("unroll 1")                                                      \
        for (int it = 0; it < DD / 32; it++) {                                   \
            CP_WAIT1();                                                          \
            __syncthreads();                                                     \
            if (it + 2 < DD / 32) G_LOAD(Asrc, Bsrc, (it + 2) * 32, (it + 2) % 3); \
            CP_COMMIT();                                                         \
            G_MMA(it % 3);                                                       \
        }                                                                        \
    } while (0)

__global__ __launch_bounds__(256) void qkv_mma(int dummy)
{
    const float* A = g_xr;
    const float* B = (blockIdx.z == 0) ? g_wqr : ((blockIdx.z == 1) ? g_wkr : g_wvr);
    float* out = (blockIdx.z == 0) ? g_q : ((blockIdx.z == 1) ? g_k : g_v);

    extern __shared__ float smem[];
    const unsigned smemBase = (unsigned)__cvta_generic_to_shared(smem);

    const int tid = threadIdx.x;
    const int w = tid >> 5, lane = tid & 31;
    const int g = lane >> 2, t = lane & 3;
    const int wm = w >> 1, wn = w & 1;

    const int rowBase = blockIdx.y * 128;
    const int colBase = blockIdx.x * 64;

    float acc[2][4][4] = {};

    G_MAINLOOP(A, B);

    // Epilogue: scatter to [b][h][n][dh]
    #pragma unroll
    for (int mi = 0; mi < 2; mi++) {
        #pragma unroll
        for (int ni = 0; ni < 4; ni++) {
            int gm0 = rowBase + wm * 32 + mi * 16 + g;
            int gn  = colBase + wn * 32 + ni * 8 + 2 * t;
            int h = gn >> 6, dh = gn & 63;
            {
                int b = gm0 >> 11, n = gm0 & (NN - 1);
                float2 v; v.x = acc[mi][ni][0]; v.y = acc[mi][ni][1];
                *(float2*)&out[(size_t)(((b * HH + h) * NN) + n) * DHH + dh] = v;
            }
            {
                int gm1 = gm0 + 8;
                int b = gm1 >> 11, n = gm1 & (NN - 1);
                float2 v; v.x = acc[mi][ni][2]; v.y = acc[mi][ni][3];
                *(float2*)&out[(size_t)(((b * HH + h) * NN) + n) * DHH + dh] = v;
            }
        }
    }
}

__global__ __launch_bounds__(256) void out_mma(
    const float* __restrict__ bo,
    float* __restrict__ y)
{
    extern __shared__ float smem[];
    const unsigned smemBase = (unsigned)__cvta_generic_to_shared(smem);

    const int tid = threadIdx.x;
    const int w = tid >> 5, lane = tid & 31;
    const int g = lane >> 2, t = lane & 3;
    const int wm = w >> 1, wn = w & 1;

    const int rowBase = blockIdx.y * 128;
    const int colBase = blockIdx.x * 64;

    float acc[2][4][4] = {};

    G_MAINLOOP(g_att, g_wor);

    #pragma unroll
    for (int mi = 0; mi < 2; mi++) {
        #pragma unroll
        for (int ni = 0; ni < 4; ni++) {
            int gm0 = rowBase + wm * 32 + mi * 16 + g;
            int gn  = colBase + wn * 32 + ni * 8 + 2 * t;
            float2 bov = *(const float2*)&bo[gn];
            float2 v0; v0.x = acc[mi][ni][0] + bov.x; v0.y = acc[mi][ni][1] + bov.y;
            float2 v1; v1.x = acc[mi][ni][2] + bov.x; v1.y = acc[mi][ni][3] + bov.y;
            *(float2*)&y[(size_t)gm0 * DD + gn] = v0;
            *(float2*)&y[(size_t)(gm0 + 8) * DD + gn] = v1;
        }
    }
}

// ---------------------------------------------------------------------------
// Kernel 2: flash attention, tf32 mma (R3-proven version).
// CTA = (b, h, 128-query tile), 8 warps.
// K tile stored k-permuted so S-phase B-frags are one ld.shared.v2.
// Output stores are tf32-rounded (consumed by cp.async out_mma).
// ---------------------------------------------------------------------------
#define KS_STRIDE 68
#define VS_STRIDE 72
#define PS_STRIDE 68

#define ATT_SMEM_FLOATS (64*KS_STRIDE + 64*VS_STRIDE + 128*PS_STRIDE + 132 + 132)

__global__ __launch_bounds__(256) void attention_mma(
    const float* __restrict__ rel_pos,
    const float* __restrict__ c_emb)
{
    extern __shared__ float sm[];
    float* Ks    = sm;                        // [64][68] permuted k
    float* Vs    = Ks + 64 * KS_STRIDE;       // [64][72]
    float* Ps    = Vs + 64 * VS_STRIDE;       // [128][68]
    float* relS  = Ps + 128 * PS_STRIDE;      // [129] pre-scaled
    float* gateS = relS + 132;                // [129]

    const int qb  = blockIdx.x;
    const int h   = blockIdx.y;
    const int b   = blockIdx.z;
    const int tid = threadIdx.x;
    const int w    = tid >> 5;
    const int lane = tid & 31;
    const int g    = lane >> 2;
    const int t    = lane & 3;

    const float* qptr = g_q + (size_t)((b * HH + h) * NN) * DHH;
    const float* kptr = g_k + (size_t)((b * HH + h) * NN) * DHH;
    const float* vptr = g_v + (size_t)((b * HH + h) * NN) * DHH;

    const int i0 = qb * 128 + w * 16;

    const float sc = 0.125f * 1.4426950408889634f;  // log2(e)/8

    for (int u = tid; u < 129; u += 256) {
        relS[u]  = rel_pos[u * HH + h] * sc;
        gateS[u] = c_emb[u * HH + h];
    }

    // Q fragments in registers, pre-scaled + tf32-rounded
    unsigned qa[8][4];
    #pragma unroll
    for (int kc = 0; kc < 8; kc++) {
        qa[kc][0] = f2tf(qptr[(i0 + g)     * DHH + kc * 8 + t]     * sc);
        qa[kc][1] = f2tf(qptr[(i0 + g + 8) * DHH + kc * 8 + t]     * sc);
        qa[kc][2] = f2tf(qptr[(i0 + g)     * DHH + kc * 8 + t + 4] * sc);
        qa[kc][3] = f2tf(qptr[(i0 + g + 8) * DHH + kc * 8 + t + 4] * sc);
    }

    float m0 = -1e30f, m1 = -1e30f, l0 = 0.f, l1 = 0.f;
    float o[8][4];
    #pragma unroll
    for (int nt = 0; nt < 8; nt++)
        #pragma unroll
        for (int j = 0; j < 4; j++) o[nt][j] = 0.f;

    for (int kb = 0; kb < NN; kb += 64) {
        __syncthreads();
        // Fill K (permuted) and V tiles: 64 rows x 64 dims each
        #pragma unroll
        for (int r4 = 0; r4 < 4; r4++) {
            int row = r4 * 16 + (tid >> 4);
            int c4  = (tid & 15) << 2;
            float4 kv = *(const float4*)&kptr[(size_t)(kb + row) * DHH + c4];
            int pbase = row * KS_STRIDE + (c4 & ~7) + ((c4 >> 2) & 1);
            Ks[pbase + 0] = kv.x;
            Ks[pbase + 2] = kv.y;
            Ks[pbase + 4] = kv.z;
            Ks[pbase + 6] = kv.w;
            float4 vv = *(const float4*)&vptr[(size_t)(kb + row) * DHH + c4];
            *(float4*)&Vs[row * VS_STRIDE + c4] = vv;
        }
        __syncthreads();

        // S = Q K^T
        float s[8][4];
        #pragma unroll
        for (int nt = 0; nt < 8; nt++) {
            float c[4] = {0.f, 0.f, 0.f, 0.f};
            #pragma unroll
            for (int kc = 0; kc < 8; kc++) {
                float2 kf = *(const float2*)&Ks[(nt * 8 + g) * KS_STRIDE + kc * 8 + 2 * t];
                unsigned bb[2];
                bb[0] = __float_as_uint(kf.x);
                bb[1] = __float_as_uint(kf.y);
                mma8(c, qa[kc], bb);
            }
            s[nt][0] = c[0]; s[nt][1] = c[1]; s[nt][2] = c[2]; s[nt][3] = c[3];
        }

        // Bias + online softmax (exp2 domain)
        const bool farhi = (kb >= i0 + 79);
        const bool farlo = (kb + 127 <= i0);
        const bool far = farhi || farlo;
        const float cb = farhi ? relS[128]  : relS[0];
        const float cg = farhi ? gateS[128] : gateS[0];

        float mx0 = -1e30f, mx1 = -1e30f;
        #pragma unroll
        for (int nt = 0; nt < 8; nt++) {
            if (far) {
                s[nt][0] += cb; s[nt][1] += cb; s[nt][2] += cb; s[nt][3] += cb;
            } else {
                int j0 = kb + nt * 8 + 2 * t;
                int d0 = j0 - (i0 + g);
                int d1 = d0 - 8;
                s[nt][0] += relS[min(max(d0,     -PP), PP) + PP];
                s[nt][1] += relS[min(max(d0 + 1, -PP), PP) + PP];
                s[nt][2] += relS[min(max(d1,     -PP), PP) + PP];
                s[nt][3] += relS[min(max(d1 + 1, -PP), PP) + PP];
            }
            mx0 = fmaxf(mx0, fmaxf(s[nt][0], s[nt][1]));
            mx1 = fmaxf(mx1, fmaxf(s[nt][2], s[nt][3]));
        }
        mx0 = fmaxf(mx0, __shfl_xor_sync(0xffffffffu, mx0, 1));
        mx0 = fmaxf(mx0, __shfl_xor_sync(0xffffffffu, mx0, 2));
        mx1 = fmaxf(mx1, __shfl_xor_sync(0xffffffffu, mx1, 1));
        mx1 = fmaxf(mx1, __shfl_xor_sync(0xffffffffu, mx1, 2));

        float mn0 = fmaxf(m0, mx0), mn1 = fmaxf(m1, mx1);
        float corr0 = ex2f(m0 - mn0), corr1 = ex2f(m1 - mn1);

        float rs0 = 0.f, rs1 = 0.f;
        const int prow0 = (w * 16 + g) * PS_STRIDE;
        const int prow1 = (w * 16 + g + 8) * PS_STRIDE;
        #pragma unroll
        for (int nt = 0; nt < 8; nt++) {
            float p00 = ex2f(s[nt][0] - mn0);
            float p01 = ex2f(s[nt][1] - mn0);
            float p10 = ex2f(s[nt][2] - mn1);
            float p11 = ex2f(s[nt][3] - mn1);
            rs0 += p00 + p01;
            rs1 += p10 + p11;
            float g00, g01, g10, g11;
            if (far) {
                g00 = g01 = g10 = g11 = cg;
            } else {
                int j0 = kb + nt * 8 + 2 * t;
                int d0 = j0 - (i0 + g);
                int d1 = d0 - 8;
                g00 = gateS[min(max(d0,     -PP), PP) + PP];
                g01 = gateS[min(max(d0 + 1, -PP), PP) + PP];
                g10 = gateS[min(max(d1,     -PP), PP) + PP];
                g11 = gateS[min(max(d1 + 1, -PP), PP) + PP];
            }
            float2 w0, w1;
            w0.x = __uint_as_float(f2tf(p00 * g00));
            w0.y = __uint_as_float(f2tf(p01 * g01));
            w1.x = __uint_as_float(f2tf(p10 * g10));
            w1.y = __uint_as_float(f2tf(p11 * g11));
            *(float2*)&Ps[prow0 + nt * 8 + 2 * t] = w0;
            *(float2*)&Ps[prow1 + nt * 8 + 2 * t] = w1;
        }
        rs0 += __shfl_xor_sync(0xffffffffu, rs0, 1);
        rs0 += __shfl_xor_sync(0xffffffffu, rs0, 2);
        rs1 += __shfl_xor_sync(0xffffffffu, rs1, 1);
        rs1 += __shfl_xor_sync(0xffffffffu, rs1, 2);

        l0 = l0 * corr0 + rs0; m0 = mn0;
        l1 = l1 * corr1 + rs1; m1 = mn1;

        #pragma unroll
        for (int nt = 0; nt < 8; nt++) {
            o[nt][0] *= corr0; o[nt][1] *= corr0;
            o[nt][2] *= corr1; o[nt][3] *= corr1;
        }

        __syncwarp();  // Ps rows are per-warp private

        // O += P V
        #pragma unroll
        for (int kc = 0; kc < 8; kc++) {
            unsigned a[4];
            a[0] = __float_as_uint(Ps[prow0 + kc * 8 + t]);
            a[1] = __float_as_uint(Ps[prow1 + kc * 8 + t]);
            a[2] = __float_as_uint(Ps[prow0 + kc * 8 + t + 4]);
            a[3] = __float_as_uint(Ps[prow1 + kc * 8 + t + 4]);
            #pragma unroll
            for (int nt = 0; nt < 8; nt++) {
                unsigned bb[2];
                bb[0] = __float_as_uint(Vs[(kc * 8 + t)     * VS_STRIDE + nt * 8 + g]);
                bb[1] = __float_as_uint(Vs[(kc * 8 + t + 4) * VS_STRIDE + nt * 8 + g]);
                mma8(o[nt], a, bb);
            }
        }
    }

    // Finalize: divide, tf32-round (out_mma consumes via cp.async), store
    float inv0 = 1.f / l0, inv1 = 1.f / l1;
    const size_t base = ((size_t)b * NN) * (HH * DHH) + h * DHH;
    const int r0 = i0 + g, r1 = i0 + g + 8;
    #pragma unroll
    for (int nt = 0; nt < 8; nt++) {
        float2 v0, v1;
        v0.x = f2tff(o[nt][0] * inv0); v0.y = f2tff(o[nt][1] * inv0);
        v1.x = f2tff(o[nt][2] * inv1); v1.y = f2tff(o[nt][3] * inv1);
        *(float2*)&g_att[base + (size_t)r0 * (HH * DHH) + nt * 8 + 2 * t] = v0;
        *(float2*)&g_att[base + (size_t)r1 * (HH * DHH) + nt * 8 + 2 * t] = v1;
    }
}

// ---------------------------------------------------------------------------
extern "C" void kernel_launch(void* const* d_in, const int* in_sizes, int n_in,
                              void* d_out, int out_size)
{
    const float* x       = (const float*)d_in[0];
    const float* Wq      = (const float*)d_in[1];
    const float* Wk      = (const float*)d_in[2];
    const float* Wv      = (const float*)d_in[3];
    const float* rel_pos = (const float*)d_in[4];
    const float* c_emb   = (const float*)d_in[5];
    const float* Wo      = (const float*)d_in[6];
    const float* bo      = (const float*)d_in[7];
    float* y             = (float*)d_out;

    round_prep<<<3072, 256>>>(x, Wq, Wk, Wv, Wo);

    cudaFuncSetAttribute(qkv_mma,
                         cudaFuncAttributeMaxDynamicSharedMemorySize,
                         GEMM_SMEM_BYTES);
    cudaFuncSetAttribute(out_mma,
                         cudaFuncAttributeMaxDynamicSharedMemorySize,
                         GEMM_SMEM_BYTES);

    dim3 gQKV(DD / 64, (BB * NN) / 128, 3);
    qkv_mma<<<gQKV, 256, GEMM_SMEM_BYTES>>>(0);

    size_t attSmem = (size_t)ATT_SMEM_FLOATS * sizeof(float);
    cudaFuncSetAttribute(attention_mma,
                         cudaFuncAttributeMaxDynamicSharedMemorySize,
                         (int)attSmem);
    dim3 gAtt(NN / 128, HH, BB);
    attention_mma<<<gAtt, 256, attSmem>>>(rel_pos, c_emb);

    dim3 gOut(DD / 64, (BB * NN) / 128);
    out_mma<<<gOut, 256, GEMM_SMEM_BYTES>>>(bo, y);
}